// round 11
// baseline (speedup 1.0000x reference)
#include <cuda_runtime.h>
#include <cuda_fp16.h>
#include <cstdint>
#include <math.h>

using f16 = __half;

#define Bsz   16384
#define DIN   1024
#define HH1   512
#define HH2   256
#define HH3   128
#define DCBP  2048
#define HC    1024
#define NCLS  10

// ---------------------------------------------------------------------------
// Scratch (allocation-free: __device__ globals). fp16 activations.
// ---------------------------------------------------------------------------
__device__ __align__(128) f16 g_in[(size_t)2 * Bsz * DIN];
__device__ __align__(128) f16 g_e1[(size_t)2 * Bsz * HH1];
__device__ __align__(128) f16 g_e2[(size_t)2 * Bsz * HH2];
__device__ __align__(128) f16 g_e3[(size_t)2 * Bsz * HH3];
__device__ __align__(128) f16 g_cbp[(size_t)Bsz * DCBP];
__device__ __align__(128) f16 g_z[(size_t)Bsz * HC];
// transposed ([N,K]) fp16 weights
__device__ __align__(128) f16 g_w1[HH1 * DIN];
__device__ __align__(128) f16 g_w2[HH2 * HH1];
__device__ __align__(128) f16 g_w3[HH3 * HH2];
__device__ __align__(128) f16 g_wc1[HC * DCBP];
// CBP pair-list structures (deterministic, rebuilt every launch)
__device__ int      g_bincnt[DCBP];
__device__ __align__(16) uint32_t g_pairs[DCBP * 64];

__device__ __forceinline__ float lrelu(float v) { return v >= 0.f ? v : 0.2f * v; }

__device__ __forceinline__ uint32_t smem_u32(const void* p) {
    uint32_t a;
    asm("{ .reg .u64 t; cvta.to.shared.u64 t, %1; cvt.u32.u64 %0, t; }" : "=r"(a) : "l"(p));
    return a;
}

#define CP16(dst, src) \
    asm volatile("cp.async.cg.shared.global [%0], [%1], 16;" :: "r"(dst), "l"(src) : "memory")
#define CP_COMMIT() asm volatile("cp.async.commit_group;" ::: "memory")
#define CP_WAIT(n)  asm volatile("cp.async.wait_group %0;" :: "n"(n) : "memory")

__device__ __forceinline__ void ldsm_x4(uint32_t& r0, uint32_t& r1, uint32_t& r2,
                                        uint32_t& r3, uint32_t addr) {
    asm volatile("ldmatrix.sync.aligned.m8n8.x4.shared.b16 {%0,%1,%2,%3}, [%4];"
                 : "=r"(r0), "=r"(r1), "=r"(r2), "=r"(r3) : "r"(addr));
}

__device__ __forceinline__ void mma16816(float* d, const uint32_t* a,
                                         uint32_t b0, uint32_t b1) {
    asm volatile(
        "mma.sync.aligned.m16n8k16.row.col.f32.f16.f16.f32 "
        "{%0,%1,%2,%3}, {%4,%5,%6,%7}, {%8,%9}, {%0,%1,%2,%3};"
        : "+f"(d[0]), "+f"(d[1]), "+f"(d[2]), "+f"(d[3])
        : "r"(a[0]), "r"(a[1]), "r"(a[2]), "r"(a[3]), "r"(b0), "r"(b1));
}

// ---------------------------------------------------------------------------
// mma_gemm<NWN>: C[M,N] = lrelu(A[M,K] @ B^T + bias), fp16 in/out, fp32 acc.
// CTA tile 128 x (64*NWN), BK=64, 3-stage cp.async pipeline, 4*NWN warps
// (4 in M x NWN in N), warp tile 32x64.  XOR-swizzled smem (no padding).
// NWN=2: 256 thr, 2 CTA/SM.  NWN=4: 512 thr, 1 CTA/SM (same 16 warps/SM).
// ---------------------------------------------------------------------------
template <int NWN>
__global__ void __launch_bounds__(128 * NWN, NWN == 2 ? 2 : 1) mma_gemm(
    const f16* __restrict__ A, const f16* __restrict__ B,
    const float* __restrict__ bias, int K, int N, f16* __restrict__ Ch)
{
    constexpr int NT   = 64 * NWN;          // CTA N-tile
    constexpr int NTHR = 128 * NWN;
    constexpr int MATB = 128 * 128;         // A bytes per stage (16384)
    constexpr int BMB  = NT * 128;          // B bytes per stage
    constexpr int STGB = MATB + BMB;
    constexpr int NCHUNK = (128 + NT) * 8;  // 16B chunks per stage

    extern __shared__ char smem[];
    const uint32_t sbase = smem_u32(smem);

    const int tid  = threadIdx.x;
    const int warp = tid >> 5, lane = tid & 31;
    const int wm = warp & 3;                // 0..3 -> M
    const int wn = warp >> 2;               // 0..NWN-1 -> N
    const int m0 = blockIdx.y * 128, n0 = blockIdx.x * NT;

    const int arow0 = wm * 32 + (lane & 15);
    const uint32_t ahi = (uint32_t)(lane >> 4);
    const uint32_t ar7 = (uint32_t)(arow0 & 7);
    const uint32_t arb0 = (uint32_t)(arow0 * 128);
    const uint32_t arb1 = (uint32_t)((arow0 + 16) * 128);

    const int brow0 = wn * 64 + (lane & 7) + ((lane >> 1) & 8);
    const uint32_t bhi = (uint32_t)((lane >> 3) & 1);
    const uint32_t br7 = (uint32_t)(brow0 & 7);
    uint32_t brb[4];
#pragma unroll
    for (int nt = 0; nt < 4; nt++) brb[nt] = (uint32_t)((brow0 + nt * 16) * 128);

    float acc[2][8][4];
#pragma unroll
    for (int i = 0; i < 2; i++)
#pragma unroll
        for (int j = 0; j < 8; j++)
#pragma unroll
            for (int q = 0; q < 4; q++) acc[i][j][q] = 0.f;

    const int nk = K >> 6;                  // BK = 64

    auto load_tile = [&](int t, int s) {
        const int kt = t << 6;
        const uint32_t sb = sbase + (uint32_t)s * STGB;
#pragma unroll
        for (int j = 0; j < NCHUNK / NTHR; j++) {
            int i = tid + j * NTHR;
            if (i < 1024) {                 // A: 128 rows x 8 chunks
                int r = i >> 3, c = i & 7;
                CP16(sb + (uint32_t)(r * 128 + ((c ^ (r & 7)) << 4)),
                     A + (size_t)(m0 + r) * K + kt + c * 8);
            } else {                        // B: NT rows x 8 chunks
                int ib = i - 1024;
                int r = ib >> 3, c = ib & 7;
                CP16(sb + (uint32_t)(MATB + r * 128 + ((c ^ (r & 7)) << 4)),
                     B + (size_t)(n0 + r) * K + kt + c * 8);
            }
        }
        CP_COMMIT();
    };

    load_tile(0, 0);
    if (nk > 1) load_tile(1, 1);

    for (int t = 0; t < nk; t++) {
        if (t + 1 < nk) { CP_WAIT(1); } else { CP_WAIT(0); }
        __syncthreads();

        if (t + 2 < nk) load_tile(t + 2, (t + 2) % 3);

        const uint32_t sb = sbase + (uint32_t)(t % 3) * STGB;

#pragma unroll
        for (int ks = 0; ks < 4; ks++) {
            const uint32_t ac = ((((uint32_t)ks << 1) + ahi) ^ ar7) << 4;
            const uint32_t bc = ((((uint32_t)ks << 1) + bhi) ^ br7) << 4;
            uint32_t ah[2][4], bb[4][4];
            ldsm_x4(ah[0][0], ah[0][1], ah[0][2], ah[0][3], sb + arb0 + ac);
            ldsm_x4(ah[1][0], ah[1][1], ah[1][2], ah[1][3], sb + arb1 + ac);
#pragma unroll
            for (int nt = 0; nt < 4; nt++)
                ldsm_x4(bb[nt][0], bb[nt][1], bb[nt][2], bb[nt][3],
                        sb + MATB + brb[nt] + bc);
#pragma unroll
            for (int mt = 0; mt < 2; mt++)
#pragma unroll
                for (int n8 = 0; n8 < 8; n8++)
                    mma16816(acc[mt][n8], ah[mt],
                             bb[n8 >> 1][(n8 & 1) * 2], bb[n8 >> 1][(n8 & 1) * 2 + 1]);
        }
    }

#pragma unroll
    for (int mt = 0; mt < 2; mt++) {
        const int r0 = m0 + wm * 32 + mt * 16 + (lane >> 2);
#pragma unroll
        for (int n8 = 0; n8 < 8; n8++) {
            const int col = n0 + wn * 64 + n8 * 8 + (lane & 3) * 2;
            const float bz0 = __ldg(bias + col), bz1 = __ldg(bias + col + 1);
            float v0 = lrelu(acc[mt][n8][0] + bz0);
            float v1 = lrelu(acc[mt][n8][1] + bz1);
            float v2 = lrelu(acc[mt][n8][2] + bz0);
            float v3 = lrelu(acc[mt][n8][3] + bz1);
            *(__half2*)(Ch + (size_t)r0 * N + col)       = __floats2half2_rn(v0, v1);
            *(__half2*)(Ch + (size_t)(r0 + 8) * N + col) = __floats2half2_rn(v2, v3);
        }
    }
}

// ---------------------------------------------------------------------------
// fp32 -> fp16 streaming convert: 8 floats -> uint4 of 8 halves per iter.
// ---------------------------------------------------------------------------
__global__ void cvt_h(const float* __restrict__ src, f16* __restrict__ h, int n8)
{
    int i = blockIdx.x * blockDim.x + threadIdx.x;
    const int stride = gridDim.x * blockDim.x;
    for (; i < n8; i += stride) {
        const float4 v0 = ((const float4*)src)[2 * i];
        const float4 v1 = ((const float4*)src)[2 * i + 1];
        __half2 a = __floats2half2_rn(v0.x, v0.y);
        __half2 b = __floats2half2_rn(v0.z, v0.w);
        __half2 c = __floats2half2_rn(v1.x, v1.y);
        __half2 d = __floats2half2_rn(v1.z, v1.w);
        uint4 o;
        o.x = *(uint32_t*)&a; o.y = *(uint32_t*)&b;
        o.z = *(uint32_t*)&c; o.w = *(uint32_t*)&d;
        ((uint4*)h)[i] = o;
    }
}

// ---------------------------------------------------------------------------
// Batched weight transpose: W[K,N] fp32 -> T[N,K] fp16, 4 segments.
// ---------------------------------------------------------------------------
__global__ void transpose_all(const float* __restrict__ W1f, const float* __restrict__ W2f,
                              const float* __restrict__ W3f, const float* __restrict__ Wc1f)
{
    const float* W; f16* T; int K, N;
    switch (blockIdx.z) {
        case 0:  W = W1f;  T = g_w1;  K = DIN;  N = HH1; break;
        case 1:  W = W2f;  T = g_w2;  K = HH1;  N = HH2; break;
        case 2:  W = W3f;  T = g_w3;  K = HH2;  N = HH3; break;
        default: W = Wc1f; T = g_wc1; K = DCBP; N = HC;  break;
    }
    if ((int)blockIdx.x >= N / 32 || (int)blockIdx.y >= K / 32) return;

    __shared__ float t[32][33];
    const int tx = threadIdx.x, ty = threadIdx.y;
    const int n = blockIdx.x * 32 + tx;
#pragma unroll
    for (int r = 0; r < 32; r += 8)
        t[ty + r][tx] = W[(size_t)(blockIdx.y * 32 + ty + r) * N + n];
    __syncthreads();
    const int k2 = blockIdx.y * 32 + tx;
#pragma unroll
    for (int r = 0; r < 32; r += 8) {
        const int n2 = blockIdx.x * 32 + ty + r;
        T[(size_t)n2 * K + k2] = __float2half_rn(t[tx][ty + r]);
    }
}

// ---------------------------------------------------------------------------
// CBP pair-list build (deterministic, no atomics, prep fused in smem).
// ---------------------------------------------------------------------------
__global__ void cbp_build(const int* __restrict__ h1, const int* __restrict__ h2)
{
    __shared__ int   icnt[DCBP];
    __shared__ short ilist[DCBP * 8];
    __shared__ int   h1s[HH3];

    const int tid = threadIdx.x;
    for (int i = tid; i < DCBP; i += 256) icnt[i] = 0;
    for (int i = tid; i < HH3; i += 256) h1s[i] = h1[i];
    __syncthreads();
    if (tid == 0) {
        for (int l = 0; l < HH3; l++) {
            int v = h2[l];
            int c = icnt[v];
            if (c < 8) { ilist[v * 8 + c] = (short)l; icnt[v] = c + 1; }
        }
    }
    __syncthreads();

    const int k = blockIdx.x * 256 + tid;
    int cnt = 0;
    const uint32_t base = (uint32_t)k * 64;
    for (int j = 0; j < HH3; j++) {
        int v = (k - h1s[j]) & (DCBP - 1);
        int c = icnt[v];
        for (int t = 0; t < c; t++) {
            if (cnt < 64)
                g_pairs[base + cnt++] = ((uint32_t)j << 16) | (uint32_t)ilist[v * 8 + t];
        }
    }
    int cnt4 = (cnt + 3) & ~3;
    if (cnt4 > 64) cnt4 = 64;
    for (int t = cnt; t < cnt4; t++) g_pairs[base + t] = (128u << 16) | 128u;
    g_bincnt[k] = cnt4;
}

// ---------------------------------------------------------------------------
// CBP main (warp-cooperative, conflict-free, exact-count quad loop).
// ---------------------------------------------------------------------------
#define CBP_AX_N  (129 * 33)
#define CBP_STG_P 257
#define CBP_SMEM  ((2 * CBP_AX_N + 32 * CBP_STG_P) * 8)

__global__ void __launch_bounds__(256) cbp_main(
    const float* __restrict__ s1, const float* __restrict__ s2)
{
    extern __shared__ uint2 csm[];
    uint2* ax    = csm;
    uint2* cy    = csm + CBP_AX_N;
    uint2* stage = csm + 2 * CBP_AX_N;

    const int b0 = blockIdx.x * 128;
    const int tid = threadIdx.x, w = tid >> 5, lane = tid & 31;

    for (int i = tid; i < 128 * 32; i += 256) {
        const int j = i & 127, sl = i >> 7;
        const size_t ex = (size_t)(b0 + 4 * sl) * HH3 + j;
        const size_t ec = (size_t)(Bsz + b0 + 4 * sl) * HH3 + j;
        uint32_t x0 = (uint32_t)__half_as_ushort(g_e3[ex])
                    | ((uint32_t)__half_as_ushort(g_e3[ex + 128]) << 16);
        uint32_t x1 = (uint32_t)__half_as_ushort(g_e3[ex + 256])
                    | ((uint32_t)__half_as_ushort(g_e3[ex + 384]) << 16);
        uint32_t y0 = (uint32_t)__half_as_ushort(g_e3[ec])
                    | ((uint32_t)__half_as_ushort(g_e3[ec + 128]) << 16);
        uint32_t y1 = (uint32_t)__half_as_ushort(g_e3[ec + 256])
                    | ((uint32_t)__half_as_ushort(g_e3[ec + 384]) << 16);
        if (s1[j] < 0.f) { x0 ^= 0x80008000u; x1 ^= 0x80008000u; }
        if (s2[j] < 0.f) { y0 ^= 0x80008000u; y1 ^= 0x80008000u; }
        ax[j * 33 + sl] = make_uint2(x0, x1);
        cy[j * 33 + sl] = make_uint2(y0, y1);
    }
    if (tid < 32) {
        ax[128 * 33 + tid] = make_uint2(0u, 0u);
        cy[128 * 33 + tid] = make_uint2(0u, 0u);
    }
    __syncthreads();

    const __half2 z2 = __floats2half2_rn(0.f, 0.f);

    for (int c = 0; c < 8; c++) {
        const int colbase = c * 256 + w * 32;
        for (int bi = 0; bi < 32; bi++) {
            const int k = colbase + bi;
            const int nq = __ldg(g_bincnt + k) >> 2;
            const uint4* pp = (const uint4*)(g_pairs + (size_t)k * 64);
            __half2 a01 = z2, a23 = z2, b01 = z2, b23 = z2;
            for (int q = 0; q < nq; q++) {
                const uint4 pv = __ldg(pp + q);
                {
                    const uint2 av = ax[(pv.x >> 16) * 33 + lane];
                    const uint2 cv = cy[(pv.x & 0xffffu) * 33 + lane];
                    a01 = __hfma2(*(const __half2*)&av.x, *(const __half2*)&cv.x, a01);
                    a23 = __hfma2(*(const __half2*)&av.y, *(const __half2*)&cv.y, a23);
                }
                {
                    const uint2 av = ax[(pv.y >> 16) * 33 + lane];
                    const uint2 cv = cy[(pv.y & 0xffffu) * 33 + lane];
                    b01 = __hfma2(*(const __half2*)&av.x, *(const __half2*)&cv.x, b01);
                    b23 = __hfma2(*(const __half2*)&av.y, *(const __half2*)&cv.y, b23);
                }
                {
                    const uint2 av = ax[(pv.z >> 16) * 33 + lane];
                    const uint2 cv = cy[(pv.z & 0xffffu) * 33 + lane];
                    a01 = __hfma2(*(const __half2*)&av.x, *(const __half2*)&cv.x, a01);
                    a23 = __hfma2(*(const __half2*)&av.y, *(const __half2*)&cv.y, a23);
                }
                {
                    const uint2 av = ax[(pv.w >> 16) * 33 + lane];
                    const uint2 cv = cy[(pv.w & 0xffffu) * 33 + lane];
                    b01 = __hfma2(*(const __half2*)&av.x, *(const __half2*)&cv.x, b01);
                    b23 = __hfma2(*(const __half2*)&av.y, *(const __half2*)&cv.y, b23);
                }
            }
            a01 = __hadd2(a01, b01);
            a23 = __hadd2(a23, b23);
            stage[lane * CBP_STG_P + w * 32 + bi] =
                make_uint2(*(const uint32_t*)&a01, *(const uint32_t*)&a23);
        }
        __syncwarp();
        for (int rp = 0; rp < 32; rp++) {
            const uint2 v = stage[rp * CBP_STG_P + w * 32 + lane];
            const __half2 v01 = *(const __half2*)&v.x;
            const __half2 v23 = *(const __half2*)&v.y;
            const size_t rb = (size_t)(b0 + 4 * rp) * DCBP + (c * 256 + w * 32 + lane);
            g_cbp[rb]            = __low2half(v01);
            g_cbp[rb + DCBP]     = __high2half(v01);
            g_cbp[rb + 2 * DCBP] = __low2half(v23);
            g_cbp[rb + 3 * DCBP] = __high2half(v23);
        }
        __syncwarp();
    }
}

// ---------------------------------------------------------------------------
// Head: logits = z @ Wc2 + bc2 (z fp16), softmax. One warp per row, 16 warps.
// ---------------------------------------------------------------------------
__global__ void __launch_bounds__(512) head_kernel(
    const float* __restrict__ Wc2, const float* __restrict__ bc2,
    float* __restrict__ out)
{
    __shared__ float Ws[HC * NCLS];
    __shared__ float bsm[NCLS];

    const int tid = threadIdx.x;
    for (int i = tid; i < HC * NCLS; i += 512) Ws[i] = Wc2[i];
    if (tid < NCLS) bsm[tid] = bc2[tid];
    __syncthreads();

    const int warp = tid >> 5, lane = tid & 31;
    const int row = blockIdx.x * 16 + warp;
    const f16* zr = g_z + (size_t)row * HC;

    float acc[NCLS];
#pragma unroll
    for (int c = 0; c < NCLS; c++) acc[c] = 0.f;
    for (int k = lane * 2; k < HC; k += 64) {
        __half2 zp = *(const __half2*)(zr + k);
        float z0 = __low2float(zp), z1 = __high2float(zp);
#pragma unroll
        for (int c = 0; c < NCLS; c++) {
            acc[c] = fmaf(z0, Ws[k * NCLS + c], acc[c]);
            acc[c] = fmaf(z1, Ws[(k + 1) * NCLS + c], acc[c]);
        }
    }
#pragma unroll
    for (int c = 0; c < NCLS; c++)
        for (int off = 16; off; off >>= 1)
            acc[c] += __shfl_down_sync(0xffffffffu, acc[c], off);

    if (lane == 0) {
        float v[NCLS], m = -1e30f;
#pragma unroll
        for (int c = 0; c < NCLS; c++) { v[c] = acc[c] + bsm[c]; m = fmaxf(m, v[c]); }
        float ssum = 0.f;
#pragma unroll
        for (int c = 0; c < NCLS; c++) { v[c] = expf(v[c] - m); ssum += v[c]; }
        float inv = 1.f / ssum;
        float* o = out + (size_t)row * NCLS;
#pragma unroll
        for (int c = 0; c < NCLS; c++) o[c] = v[c] * inv;
    }
}

// ---------------------------------------------------------------------------
extern "C" void kernel_launch(void* const* d_in, const int* in_sizes, int n_in,
                              void* d_out, int out_size)
{
    const float* X   = (const float*)d_in[0];
    const float* Cn  = (const float*)d_in[1];
    const float* W1  = (const float*)d_in[2];
    const float* b1  = (const float*)d_in[3];
    const float* W2  = (const float*)d_in[4];
    const float* b2  = (const float*)d_in[5];
    const float* W3  = (const float*)d_in[6];
    const float* b3  = (const float*)d_in[7];
    const int*   h1  = (const int*)d_in[8];
    const float* s1  = (const float*)d_in[9];
    const int*   h2  = (const int*)d_in[10];
    const float* s2  = (const float*)d_in[11];
    const float* Wc1 = (const float*)d_in[12];
    const float* bc1 = (const float*)d_in[13];
    const float* Wc2 = (const float*)d_in[14];
    const float* bc2 = (const float*)d_in[15];
    float* out = (float*)d_out;

    f16 *in_, *e1, *e2, *e3, *cbp, *z, *w1, *w2, *w3, *wc1;
    cudaGetSymbolAddress((void**)&in_, g_in);
    cudaGetSymbolAddress((void**)&e1,  g_e1);
    cudaGetSymbolAddress((void**)&e2,  g_e2);
    cudaGetSymbolAddress((void**)&e3,  g_e3);
    cudaGetSymbolAddress((void**)&cbp, g_cbp);
    cudaGetSymbolAddress((void**)&z,   g_z);
    cudaGetSymbolAddress((void**)&w1,  g_w1);
    cudaGetSymbolAddress((void**)&w2,  g_w2);
    cudaGetSymbolAddress((void**)&w3,  g_w3);
    cudaGetSymbolAddress((void**)&wc1, g_wc1);

    constexpr int SMEM128 = 3 * (16384 + 128 * 128);   //  98304
    constexpr int SMEM256 = 3 * (16384 + 256 * 128);   // 147456
    cudaFuncSetAttribute((const void*)mma_gemm<2>,
                         cudaFuncAttributeMaxDynamicSharedMemorySize, SMEM128);
    cudaFuncSetAttribute((const void*)mma_gemm<4>,
                         cudaFuncAttributeMaxDynamicSharedMemorySize, SMEM256);
    cudaFuncSetAttribute((const void*)cbp_main,
                         cudaFuncAttributeMaxDynamicSharedMemorySize, CBP_SMEM);

    const int n8 = Bsz * DIN / 8;

    // idx 3 = gemm1 (NWN=4, 512 thr) -- this round's profiling target.
    cvt_h<<<2048, 256>>>(X,  in_,                     n8);                          // 0
    transpose_all<<<dim3(32, 64, 4), dim3(32, 8)>>>(W1, W2, W3, Wc1);               // 1
    cvt_h<<<2048, 256>>>(Cn, in_ + (size_t)Bsz * DIN, n8);                          // 2
    mma_gemm<4><<<dim3(HH1 / 256, 2 * Bsz / 128), 512, SMEM256>>>(                  // 3 (profiled)
        in_, w1, b1, DIN, HH1, e1);
    cbp_build<<<8, 256>>>(h1, h2);                                                  // 4
    mma_gemm<4><<<dim3(HH2 / 256, 2 * Bsz / 128), 512, SMEM256>>>(                  // 5
        e1, w2, b2, HH1, HH2, e2);
    mma_gemm<2><<<dim3(HH3 / 128, 2 * Bsz / 128), 256, SMEM128>>>(                  // 6
        e2, w3, b3, HH2, HH3, e3);
    cbp_main<<<Bsz / 128, 256, CBP_SMEM>>>(s1, s2);                                 // 7
    mma_gemm<4><<<dim3(HC / 256, Bsz / 128), 512, SMEM256>>>(                       // 8
        cbp, wc1, bc1, DCBP, HC, z);
    head_kernel<<<Bsz / 16, 512>>>(Wc2, bc2, out);                                  // 9
}

// round 12
// speedup vs baseline: 1.0614x; 1.0614x over previous
#include <cuda_runtime.h>
#include <cuda_fp16.h>
#include <cstdint>
#include <math.h>

using f16 = __half;

#define Bsz   16384
#define DIN   1024
#define HH1   512
#define HH2   256
#define HH3   128
#define DCBP  2048
#define HC    1024
#define NCLS  10

// ---------------------------------------------------------------------------
// Scratch (allocation-free: __device__ globals). fp16 activations.
// ---------------------------------------------------------------------------
__device__ __align__(128) f16 g_in[(size_t)2 * Bsz * DIN];
__device__ __align__(128) f16 g_e1[(size_t)2 * Bsz * HH1];
__device__ __align__(128) f16 g_e2[(size_t)2 * Bsz * HH2];
__device__ __align__(128) f16 g_e3[(size_t)2 * Bsz * HH3];
__device__ __align__(128) f16 g_cbp[(size_t)Bsz * DCBP];
__device__ __align__(128) f16 g_z[(size_t)Bsz * HC];
// transposed ([N,K]) fp16 weights
__device__ __align__(128) f16 g_w1[HH1 * DIN];
__device__ __align__(128) f16 g_w2[HH2 * HH1];
__device__ __align__(128) f16 g_w3[HH3 * HH2];
__device__ __align__(128) f16 g_wc1[HC * DCBP];
// CBP pair-list structures (deterministic, rebuilt every launch)
__device__ int      g_bincnt[DCBP];
__device__ __align__(16) uint32_t g_pairs[DCBP * 64];

__device__ __forceinline__ float lrelu(float v) { return v >= 0.f ? v : 0.2f * v; }

__device__ __forceinline__ uint32_t smem_u32(const void* p) {
    uint32_t a;
    asm("{ .reg .u64 t; cvta.to.shared.u64 t, %1; cvt.u32.u64 %0, t; }" : "=r"(a) : "l"(p));
    return a;
}

#define CP16(dst, src) \
    asm volatile("cp.async.cg.shared.global [%0], [%1], 16;" :: "r"(dst), "l"(src) : "memory")
#define CP_COMMIT() asm volatile("cp.async.commit_group;" ::: "memory")
#define CP_WAIT(n)  asm volatile("cp.async.wait_group %0;" :: "n"(n) : "memory")

__device__ __forceinline__ void ldsm_x4(uint32_t& r0, uint32_t& r1, uint32_t& r2,
                                        uint32_t& r3, uint32_t addr) {
    asm volatile("ldmatrix.sync.aligned.m8n8.x4.shared.b16 {%0,%1,%2,%3}, [%4];"
                 : "=r"(r0), "=r"(r1), "=r"(r2), "=r"(r3) : "r"(addr));
}

__device__ __forceinline__ void mma16816(float* d, const uint32_t* a,
                                         uint32_t b0, uint32_t b1) {
    asm volatile(
        "mma.sync.aligned.m16n8k16.row.col.f32.f16.f16.f32 "
        "{%0,%1,%2,%3}, {%4,%5,%6,%7}, {%8,%9}, {%0,%1,%2,%3};"
        : "+f"(d[0]), "+f"(d[1]), "+f"(d[2]), "+f"(d[3])
        : "r"(a[0]), "r"(a[1]), "r"(a[2]), "r"(a[3]), "r"(b0), "r"(b1));
}

// ---------------------------------------------------------------------------
// mma_gemm: persistent-CTA tiled GEMM.  C[M,N] = lrelu(A @ B^T + bias),
// fp16 in/out, fp32 acc.  CTA tile 128x128, BK=64, 3-stage cp.async pipeline,
// 8 warps (4M x 2N), 2 CTA/SM.  CTAs grid-stride over nbx*nby tiles
// (bx fastest -> concurrent CTAs share the A tile in L2).
// ---------------------------------------------------------------------------
__global__ void __launch_bounds__(256, 2) mma_gemm(
    const f16* __restrict__ A, const f16* __restrict__ B,
    const float* __restrict__ bias, int K, int N, f16* __restrict__ Ch,
    int nbx, int nby)
{
    constexpr int MATB = 128 * 128;     // 16384 B per matrix per stage
    constexpr int STGB = 2 * MATB;      // 32768 B per stage

    extern __shared__ char smem[];
    const uint32_t sbase = smem_u32(smem);

    const int tid  = threadIdx.x;
    const int warp = tid >> 5, lane = tid & 31;
    const int wm = warp & 3;            // 0..3 -> M
    const int wn = warp >> 2;           // 0..1 -> N

    const int arow0 = wm * 32 + (lane & 15);
    const uint32_t ahi = (uint32_t)(lane >> 4);
    const uint32_t ar7 = (uint32_t)(arow0 & 7);
    const uint32_t arb0 = (uint32_t)(arow0 * 128);
    const uint32_t arb1 = (uint32_t)((arow0 + 16) * 128);

    const int brow0 = wn * 64 + (lane & 7) + ((lane >> 1) & 8);
    const uint32_t bhi = (uint32_t)((lane >> 3) & 1);
    const uint32_t br7 = (uint32_t)(brow0 & 7);
    uint32_t brb[4];
#pragma unroll
    for (int nt = 0; nt < 4; nt++) brb[nt] = (uint32_t)((brow0 + nt * 16) * 128);

    const int nk = K >> 6;              // BK = 64
    const int ntiles = nbx * nby;

    for (int tile = blockIdx.x; tile < ntiles; tile += gridDim.x) {
        const int m0 = (tile / nbx) * 128;
        const int n0 = (tile % nbx) * 128;

        auto load_tile = [&](int t, int s) {
            const int kt = t << 6;
            const uint32_t sb = sbase + (uint32_t)s * STGB;
#pragma unroll
            for (int j = 0; j < 8; j++) {
                int i = tid + j * 256;
                int mat = i >> 10;
                int r = (i >> 3) & 127, c = i & 7;
                const f16* src = mat ? (B + (size_t)(n0 + r) * K + kt + c * 8)
                                     : (A + (size_t)(m0 + r) * K + kt + c * 8);
                CP16(sb + (uint32_t)(mat * MATB + r * 128 + ((c ^ (r & 7)) << 4)), src);
            }
            CP_COMMIT();
        };

        float acc[2][8][4];
#pragma unroll
        for (int i = 0; i < 2; i++)
#pragma unroll
            for (int j = 0; j < 8; j++)
#pragma unroll
                for (int q = 0; q < 4; q++) acc[i][j][q] = 0.f;

        __syncthreads();                // all warps done reading previous tile's stages
        load_tile(0, 0);
        if (nk > 1) load_tile(1, 1);

        for (int t = 0; t < nk; t++) {
            if (t + 1 < nk) { CP_WAIT(1); } else { CP_WAIT(0); }
            __syncthreads();

            if (t + 2 < nk) load_tile(t + 2, (t + 2) % 3);

            const uint32_t sb = sbase + (uint32_t)(t % 3) * STGB;

#pragma unroll
            for (int ks = 0; ks < 4; ks++) {
                const uint32_t ac = ((((uint32_t)ks << 1) + ahi) ^ ar7) << 4;
                const uint32_t bc = ((((uint32_t)ks << 1) + bhi) ^ br7) << 4;
                uint32_t ah[2][4], bb[4][4];
                ldsm_x4(ah[0][0], ah[0][1], ah[0][2], ah[0][3], sb + arb0 + ac);
                ldsm_x4(ah[1][0], ah[1][1], ah[1][2], ah[1][3], sb + arb1 + ac);
#pragma unroll
                for (int nt = 0; nt < 4; nt++)
                    ldsm_x4(bb[nt][0], bb[nt][1], bb[nt][2], bb[nt][3],
                            sb + MATB + brb[nt] + bc);
#pragma unroll
                for (int mt = 0; mt < 2; mt++)
#pragma unroll
                    for (int n8 = 0; n8 < 8; n8++)
                        mma16816(acc[mt][n8], ah[mt],
                                 bb[n8 >> 1][(n8 & 1) * 2], bb[n8 >> 1][(n8 & 1) * 2 + 1]);
            }
        }

#pragma unroll
        for (int mt = 0; mt < 2; mt++) {
            const int r0 = m0 + wm * 32 + mt * 16 + (lane >> 2);
#pragma unroll
            for (int n8 = 0; n8 < 8; n8++) {
                const int col = n0 + wn * 64 + n8 * 8 + (lane & 3) * 2;
                const float bz0 = __ldg(bias + col), bz1 = __ldg(bias + col + 1);
                float v0 = lrelu(acc[mt][n8][0] + bz0);
                float v1 = lrelu(acc[mt][n8][1] + bz1);
                float v2 = lrelu(acc[mt][n8][2] + bz0);
                float v3 = lrelu(acc[mt][n8][3] + bz1);
                *(__half2*)(Ch + (size_t)r0 * N + col)       = __floats2half2_rn(v0, v1);
                *(__half2*)(Ch + (size_t)(r0 + 8) * N + col) = __floats2half2_rn(v2, v3);
            }
        }
    }
}

// ---------------------------------------------------------------------------
// fp32 -> fp16, both inputs in one launch: 8 floats -> uint4 of 8 halves.
// ---------------------------------------------------------------------------
__global__ void cvt_both(const float* __restrict__ X, const float* __restrict__ Cn,
                         f16* __restrict__ h, int n8half)
{
    int i = blockIdx.x * blockDim.x + threadIdx.x;
    const int stride = gridDim.x * blockDim.x;
    for (; i < 2 * n8half; i += stride) {
        const float4* src = (i < n8half) ? ((const float4*)X) + 2 * i
                                         : ((const float4*)Cn) + 2 * (i - n8half);
        const float4 v0 = src[0];
        const float4 v1 = src[1];
        __half2 a = __floats2half2_rn(v0.x, v0.y);
        __half2 b = __floats2half2_rn(v0.z, v0.w);
        __half2 c = __floats2half2_rn(v1.x, v1.y);
        __half2 d = __floats2half2_rn(v1.z, v1.w);
        uint4 o;
        o.x = *(uint32_t*)&a; o.y = *(uint32_t*)&b;
        o.z = *(uint32_t*)&c; o.w = *(uint32_t*)&d;
        ((uint4*)h)[i] = o;
    }
}

// ---------------------------------------------------------------------------
// Batched weight transpose: W[K,N] fp32 -> T[N,K] fp16, 4 segments.
// ---------------------------------------------------------------------------
__global__ void transpose_all(const float* __restrict__ W1f, const float* __restrict__ W2f,
                              const float* __restrict__ W3f, const float* __restrict__ Wc1f)
{
    const float* W; f16* T; int K, N;
    switch (blockIdx.z) {
        case 0:  W = W1f;  T = g_w1;  K = DIN;  N = HH1; break;
        case 1:  W = W2f;  T = g_w2;  K = HH1;  N = HH2; break;
        case 2:  W = W3f;  T = g_w3;  K = HH2;  N = HH3; break;
        default: W = Wc1f; T = g_wc1; K = DCBP; N = HC;  break;
    }
    if ((int)blockIdx.x >= N / 32 || (int)blockIdx.y >= K / 32) return;

    __shared__ float t[32][33];
    const int tx = threadIdx.x, ty = threadIdx.y;
    const int n = blockIdx.x * 32 + tx;
#pragma unroll
    for (int r = 0; r < 32; r += 8)
        t[ty + r][tx] = W[(size_t)(blockIdx.y * 32 + ty + r) * N + n];
    __syncthreads();
    const int k2 = blockIdx.y * 32 + tx;
#pragma unroll
    for (int r = 0; r < 32; r += 8) {
        const int n2 = blockIdx.x * 32 + ty + r;
        T[(size_t)n2 * K + k2] = __float2half_rn(t[tx][ty + r]);
    }
}

// ---------------------------------------------------------------------------
// CBP pair-list build (deterministic, no atomics, prep fused in smem).
// ---------------------------------------------------------------------------
__global__ void cbp_build(const int* __restrict__ h1, const int* __restrict__ h2)
{
    __shared__ int   icnt[DCBP];
    __shared__ short ilist[DCBP * 8];
    __shared__ int   h1s[HH3];

    const int tid = threadIdx.x;
    for (int i = tid; i < DCBP; i += 256) icnt[i] = 0;
    for (int i = tid; i < HH3; i += 256) h1s[i] = h1[i];
    __syncthreads();
    if (tid == 0) {
        for (int l = 0; l < HH3; l++) {
            int v = h2[l];
            int c = icnt[v];
            if (c < 8) { ilist[v * 8 + c] = (short)l; icnt[v] = c + 1; }
        }
    }
    __syncthreads();

    const int k = blockIdx.x * 256 + tid;
    int cnt = 0;
    const uint32_t base = (uint32_t)k * 64;
    for (int j = 0; j < HH3; j++) {
        int v = (k - h1s[j]) & (DCBP - 1);
        int c = icnt[v];
        for (int t = 0; t < c; t++) {
            if (cnt < 64)
                g_pairs[base + cnt++] = ((uint32_t)j << 16) | (uint32_t)ilist[v * 8 + t];
        }
    }
    int cnt4 = (cnt + 3) & ~3;
    if (cnt4 > 64) cnt4 = 64;
    for (int t = cnt; t < cnt4; t++) g_pairs[base + t] = (128u << 16) | 128u;
    g_bincnt[k] = cnt4;
}

// ---------------------------------------------------------------------------
// CBP main (warp-cooperative, conflict-free, exact-count quad loop).
// ---------------------------------------------------------------------------
#define CBP_AX_N  (129 * 33)
#define CBP_STG_P 257
#define CBP_SMEM  ((2 * CBP_AX_N + 32 * CBP_STG_P) * 8)

__global__ void __launch_bounds__(256) cbp_main(
    const float* __restrict__ s1, const float* __restrict__ s2)
{
    extern __shared__ uint2 csm[];
    uint2* ax    = csm;
    uint2* cy    = csm + CBP_AX_N;
    uint2* stage = csm + 2 * CBP_AX_N;

    const int b0 = blockIdx.x * 128;
    const int tid = threadIdx.x, w = tid >> 5, lane = tid & 31;

    for (int i = tid; i < 128 * 32; i += 256) {
        const int j = i & 127, sl = i >> 7;
        const size_t ex = (size_t)(b0 + 4 * sl) * HH3 + j;
        const size_t ec = (size_t)(Bsz + b0 + 4 * sl) * HH3 + j;
        uint32_t x0 = (uint32_t)__half_as_ushort(g_e3[ex])
                    | ((uint32_t)__half_as_ushort(g_e3[ex + 128]) << 16);
        uint32_t x1 = (uint32_t)__half_as_ushort(g_e3[ex + 256])
                    | ((uint32_t)__half_as_ushort(g_e3[ex + 384]) << 16);
        uint32_t y0 = (uint32_t)__half_as_ushort(g_e3[ec])
                    | ((uint32_t)__half_as_ushort(g_e3[ec + 128]) << 16);
        uint32_t y1 = (uint32_t)__half_as_ushort(g_e3[ec + 256])
                    | ((uint32_t)__half_as_ushort(g_e3[ec + 384]) << 16);
        if (s1[j] < 0.f) { x0 ^= 0x80008000u; x1 ^= 0x80008000u; }
        if (s2[j] < 0.f) { y0 ^= 0x80008000u; y1 ^= 0x80008000u; }
        ax[j * 33 + sl] = make_uint2(x0, x1);
        cy[j * 33 + sl] = make_uint2(y0, y1);
    }
    if (tid < 32) {
        ax[128 * 33 + tid] = make_uint2(0u, 0u);
        cy[128 * 33 + tid] = make_uint2(0u, 0u);
    }
    __syncthreads();

    const __half2 z2 = __floats2half2_rn(0.f, 0.f);

    for (int c = 0; c < 8; c++) {
        const int colbase = c * 256 + w * 32;
        for (int bi = 0; bi < 32; bi++) {
            const int k = colbase + bi;
            const int nq = __ldg(g_bincnt + k) >> 2;
            const uint4* pp = (const uint4*)(g_pairs + (size_t)k * 64);
            __half2 a01 = z2, a23 = z2, b01 = z2, b23 = z2;
            for (int q = 0; q < nq; q++) {
                const uint4 pv = __ldg(pp + q);
                {
                    const uint2 av = ax[(pv.x >> 16) * 33 + lane];
                    const uint2 cv = cy[(pv.x & 0xffffu) * 33 + lane];
                    a01 = __hfma2(*(const __half2*)&av.x, *(const __half2*)&cv.x, a01);
                    a23 = __hfma2(*(const __half2*)&av.y, *(const __half2*)&cv.y, a23);
                }
                {
                    const uint2 av = ax[(pv.y >> 16) * 33 + lane];
                    const uint2 cv = cy[(pv.y & 0xffffu) * 33 + lane];
                    b01 = __hfma2(*(const __half2*)&av.x, *(const __half2*)&cv.x, b01);
                    b23 = __hfma2(*(const __half2*)&av.y, *(const __half2*)&cv.y, b23);
                }
                {
                    const uint2 av = ax[(pv.z >> 16) * 33 + lane];
                    const uint2 cv = cy[(pv.z & 0xffffu) * 33 + lane];
                    a01 = __hfma2(*(const __half2*)&av.x, *(const __half2*)&cv.x, a01);
                    a23 = __hfma2(*(const __half2*)&av.y, *(const __half2*)&cv.y, a23);
                }
                {
                    const uint2 av = ax[(pv.w >> 16) * 33 + lane];
                    const uint2 cv = cy[(pv.w & 0xffffu) * 33 + lane];
                    b01 = __hfma2(*(const __half2*)&av.x, *(const __half2*)&cv.x, b01);
                    b23 = __hfma2(*(const __half2*)&av.y, *(const __half2*)&cv.y, b23);
                }
            }
            a01 = __hadd2(a01, b01);
            a23 = __hadd2(a23, b23);
            stage[lane * CBP_STG_P + w * 32 + bi] =
                make_uint2(*(const uint32_t*)&a01, *(const uint32_t*)&a23);
        }
        __syncwarp();
        for (int rp = 0; rp < 32; rp++) {
            const uint2 v = stage[rp * CBP_STG_P + w * 32 + lane];
            const __half2 v01 = *(const __half2*)&v.x;
            const __half2 v23 = *(const __half2*)&v.y;
            const size_t rb = (size_t)(b0 + 4 * rp) * DCBP + (c * 256 + w * 32 + lane);
            g_cbp[rb]            = __low2half(v01);
            g_cbp[rb + DCBP]     = __high2half(v01);
            g_cbp[rb + 2 * DCBP] = __low2half(v23);
            g_cbp[rb + 3 * DCBP] = __high2half(v23);
        }
        __syncwarp();
    }
}

// ---------------------------------------------------------------------------
// Head: logits = z @ Wc2 + bc2 (z fp16), softmax. One warp per row, 16 warps.
// ---------------------------------------------------------------------------
__global__ void __launch_bounds__(512) head_kernel(
    const float* __restrict__ Wc2, const float* __restrict__ bc2,
    float* __restrict__ out)
{
    __shared__ float Ws[HC * NCLS];
    __shared__ float bsm[NCLS];

    const int tid = threadIdx.x;
    for (int i = tid; i < HC * NCLS; i += 512) Ws[i] = Wc2[i];
    if (tid < NCLS) bsm[tid] = bc2[tid];
    __syncthreads();

    const int warp = tid >> 5, lane = tid & 31;
    const int row = blockIdx.x * 16 + warp;
    const f16* zr = g_z + (size_t)row * HC;

    float acc[NCLS];
#pragma unroll
    for (int c = 0; c < NCLS; c++) acc[c] = 0.f;
    for (int k = lane * 2; k < HC; k += 64) {
        __half2 zp = *(const __half2*)(zr + k);
        float z0 = __low2float(zp), z1 = __high2float(zp);
#pragma unroll
        for (int c = 0; c < NCLS; c++) {
            acc[c] = fmaf(z0, Ws[k * NCLS + c], acc[c]);
            acc[c] = fmaf(z1, Ws[(k + 1) * NCLS + c], acc[c]);
        }
    }
#pragma unroll
    for (int c = 0; c < NCLS; c++)
        for (int off = 16; off; off >>= 1)
            acc[c] += __shfl_down_sync(0xffffffffu, acc[c], off);

    if (lane == 0) {
        float v[NCLS], m = -1e30f;
#pragma unroll
        for (int c = 0; c < NCLS; c++) { v[c] = acc[c] + bsm[c]; m = fmaxf(m, v[c]); }
        float ssum = 0.f;
#pragma unroll
        for (int c = 0; c < NCLS; c++) { v[c] = expf(v[c] - m); ssum += v[c]; }
        float inv = 1.f / ssum;
        float* o = out + (size_t)row * NCLS;
#pragma unroll
        for (int c = 0; c < NCLS; c++) o[c] = v[c] * inv;
    }
}

// ---------------------------------------------------------------------------
extern "C" void kernel_launch(void* const* d_in, const int* in_sizes, int n_in,
                              void* d_out, int out_size)
{
    const float* X   = (const float*)d_in[0];
    const float* Cn  = (const float*)d_in[1];
    const float* W1  = (const float*)d_in[2];
    const float* b1  = (const float*)d_in[3];
    const float* W2  = (const float*)d_in[4];
    const float* b2  = (const float*)d_in[5];
    const float* W3  = (const float*)d_in[6];
    const float* b3  = (const float*)d_in[7];
    const int*   h1  = (const int*)d_in[8];
    const float* s1  = (const float*)d_in[9];
    const int*   h2  = (const int*)d_in[10];
    const float* s2  = (const float*)d_in[11];
    const float* Wc1 = (const float*)d_in[12];
    const float* bc1 = (const float*)d_in[13];
    const float* Wc2 = (const float*)d_in[14];
    const float* bc2 = (const float*)d_in[15];
    float* out = (float*)d_out;

    f16 *in_, *e1, *e2, *e3, *cbp, *z, *w1, *w2, *w3, *wc1;
    cudaGetSymbolAddress((void**)&in_, g_in);
    cudaGetSymbolAddress((void**)&e1,  g_e1);
    cudaGetSymbolAddress((void**)&e2,  g_e2);
    cudaGetSymbolAddress((void**)&e3,  g_e3);
    cudaGetSymbolAddress((void**)&cbp, g_cbp);
    cudaGetSymbolAddress((void**)&z,   g_z);
    cudaGetSymbolAddress((void**)&w1,  g_w1);
    cudaGetSymbolAddress((void**)&w2,  g_w2);
    cudaGetSymbolAddress((void**)&w3,  g_w3);
    cudaGetSymbolAddress((void**)&wc1, g_wc1);

    constexpr int SMEM = 3 * 32768;
    cudaFuncSetAttribute((const void*)mma_gemm,
                         cudaFuncAttributeMaxDynamicSharedMemorySize, SMEM);
    cudaFuncSetAttribute((const void*)cbp_main,
                         cudaFuncAttributeMaxDynamicSharedMemorySize, CBP_SMEM);

    const int n8h = Bsz * DIN / 8;
    const int NPERS = 296;  // 2 CTAs/SM x 148 SMs

    auto grid_for = [](int ntiles) { return ntiles < 296 ? ntiles : 296; };

    // idx 3 = gemm1 (persistent) -- profiling target.
    cvt_both<<<4096, 256>>>(X, Cn, in_, n8h);                                       // 0
    transpose_all<<<dim3(32, 64, 4), dim3(32, 8)>>>(W1, W2, W3, Wc1);               // 1
    cbp_build<<<8, 256>>>(h1, h2);                                                  // 2
    mma_gemm<<<grid_for(4 * 256), 256, SMEM>>>(                                     // 3 (profiled)
        in_, w1, b1, DIN, HH1, e1, 4, 256);
    mma_gemm<<<grid_for(2 * 256), 256, SMEM>>>(                                     // 4
        e1, w2, b2, HH1, HH2, e2, 2, 256);
    mma_gemm<<<grid_for(1 * 256), 256, SMEM>>>(                                     // 5
        e2, w3, b3, HH2, HH3, e3, 1, 256);
    cbp_main<<<Bsz / 128, 256, CBP_SMEM>>>(s1, s2);                                 // 6
    mma_gemm<<<grid_for(8 * 128), 256, SMEM>>>(                                     // 7
        cbp, wc1, bc1, DCBP, HC, z, 8, 128);
    head_kernel<<<Bsz / 16, 512>>>(Wc2, bc2, out);                                  // 8
    (void)NPERS;
}

// round 13
// speedup vs baseline: 1.0927x; 1.0294x over previous
#include <cuda_runtime.h>
#include <cuda_fp16.h>
#include <cstdint>
#include <math.h>

using f16 = __half;

#define Bsz   16384
#define DIN   1024
#define HH1   512
#define HH2   256
#define HH3   128
#define DCBP  2048
#define HC    1024
#define NCLS  10

// ---------------------------------------------------------------------------
// Scratch (allocation-free: __device__ globals). fp16 activations.
// ---------------------------------------------------------------------------
__device__ __align__(128) f16 g_in[(size_t)2 * Bsz * DIN];
__device__ __align__(128) f16 g_e1[(size_t)2 * Bsz * HH1];
__device__ __align__(128) f16 g_e2[(size_t)2 * Bsz * HH2];
__device__ __align__(128) f16 g_e3[(size_t)2 * Bsz * HH3];
__device__ __align__(128) f16 g_cbp[(size_t)Bsz * DCBP];
__device__ __align__(128) f16 g_z[(size_t)Bsz * HC];
// transposed ([N,K]) fp16 weights
__device__ __align__(128) f16 g_w1[HH1 * DIN];
__device__ __align__(128) f16 g_w2[HH2 * HH1];
__device__ __align__(128) f16 g_w3[HH3 * HH2];
__device__ __align__(128) f16 g_wc1[HC * DCBP];
// CBP pair-list structures (deterministic, rebuilt every launch)
__device__ int      g_bincnt[DCBP];
__device__ __align__(16) uint32_t g_pairs[DCBP * 64];

__device__ __forceinline__ float lrelu(float v) { return v >= 0.f ? v : 0.2f * v; }

__device__ __forceinline__ uint32_t smem_u32(const void* p) {
    uint32_t a;
    asm("{ .reg .u64 t; cvta.to.shared.u64 t, %1; cvt.u32.u64 %0, t; }" : "=r"(a) : "l"(p));
    return a;
}

#define CP16(dst, src) \
    asm volatile("cp.async.cg.shared.global [%0], [%1], 16;" :: "r"(dst), "l"(src) : "memory")
#define CP_COMMIT() asm volatile("cp.async.commit_group;" ::: "memory")
#define CP_WAIT(n)  asm volatile("cp.async.wait_group %0;" :: "n"(n) : "memory")

__device__ __forceinline__ void ldsm_x4(uint32_t& r0, uint32_t& r1, uint32_t& r2,
                                        uint32_t& r3, uint32_t addr) {
    asm volatile("ldmatrix.sync.aligned.m8n8.x4.shared.b16 {%0,%1,%2,%3}, [%4];"
                 : "=r"(r0), "=r"(r1), "=r"(r2), "=r"(r3) : "r"(addr));
}

__device__ __forceinline__ void mma16816(float* d, const uint32_t* a,
                                         uint32_t b0, uint32_t b1) {
    asm volatile(
        "mma.sync.aligned.m16n8k16.row.col.f32.f16.f16.f32 "
        "{%0,%1,%2,%3}, {%4,%5,%6,%7}, {%8,%9}, {%0,%1,%2,%3};"
        : "+f"(d[0]), "+f"(d[1]), "+f"(d[2]), "+f"(d[3])
        : "r"(a[0]), "r"(a[1]), "r"(a[2]), "r"(a[3]), "r"(b0), "r"(b1));
}

// ---------------------------------------------------------------------------
// mma_gemm: C[M,N] = lrelu(A[M,K] @ B^T + bias), fp16 in/out, fp32 acc.
// CTA tile 128x128, BK=64, 3-stage cp.async pipeline, 8 warps (4M x 2N),
// 2 CTA/SM.  XOR-swizzled smem.  (Proven R10 configuration.)
// ---------------------------------------------------------------------------
__global__ void __launch_bounds__(256, 2) mma_gemm(
    const f16* __restrict__ A, const f16* __restrict__ B,
    const float* __restrict__ bias, int K, int N, f16* __restrict__ Ch)
{
    constexpr int MATB = 128 * 128;     // 16384 B per matrix per stage
    constexpr int STGB = 2 * MATB;      // 32768 B per stage

    extern __shared__ char smem[];
    const uint32_t sbase = smem_u32(smem);

    const int tid  = threadIdx.x;
    const int warp = tid >> 5, lane = tid & 31;
    const int wm = warp & 3;            // 0..3 -> M
    const int wn = warp >> 2;           // 0..1 -> N
    const int m0 = blockIdx.y * 128, n0 = blockIdx.x * 128;

    const int arow0 = wm * 32 + (lane & 15);
    const uint32_t ahi = (uint32_t)(lane >> 4);
    const uint32_t ar7 = (uint32_t)(arow0 & 7);
    const uint32_t arb0 = (uint32_t)(arow0 * 128);
    const uint32_t arb1 = (uint32_t)((arow0 + 16) * 128);

    const int brow0 = wn * 64 + (lane & 7) + ((lane >> 1) & 8);
    const uint32_t bhi = (uint32_t)((lane >> 3) & 1);
    const uint32_t br7 = (uint32_t)(brow0 & 7);
    uint32_t brb[4];
#pragma unroll
    for (int nt = 0; nt < 4; nt++) brb[nt] = (uint32_t)((brow0 + nt * 16) * 128);

    float acc[2][8][4];
#pragma unroll
    for (int i = 0; i < 2; i++)
#pragma unroll
        for (int j = 0; j < 8; j++)
#pragma unroll
            for (int q = 0; q < 4; q++) acc[i][j][q] = 0.f;

    const int nk = K >> 6;              // BK = 64

    auto load_tile = [&](int t, int s) {
        const int kt = t << 6;
        const uint32_t sb = sbase + (uint32_t)s * STGB;
#pragma unroll
        for (int j = 0; j < 8; j++) {
            int i = tid + j * 256;
            int mat = i >> 10;
            int r = (i >> 3) & 127, c = i & 7;
            const f16* src = mat ? (B + (size_t)(n0 + r) * K + kt + c * 8)
                                 : (A + (size_t)(m0 + r) * K + kt + c * 8);
            CP16(sb + (uint32_t)(mat * MATB + r * 128 + ((c ^ (r & 7)) << 4)), src);
        }
        CP_COMMIT();
    };

    load_tile(0, 0);
    if (nk > 1) load_tile(1, 1);

    for (int t = 0; t < nk; t++) {
        if (t + 1 < nk) { CP_WAIT(1); } else { CP_WAIT(0); }
        __syncthreads();

        if (t + 2 < nk) load_tile(t + 2, (t + 2) % 3);

        const uint32_t sb = sbase + (uint32_t)(t % 3) * STGB;

#pragma unroll
        for (int ks = 0; ks < 4; ks++) {
            const uint32_t ac = ((((uint32_t)ks << 1) + ahi) ^ ar7) << 4;
            const uint32_t bc = ((((uint32_t)ks << 1) + bhi) ^ br7) << 4;
            uint32_t ah[2][4], bb[4][4];
            ldsm_x4(ah[0][0], ah[0][1], ah[0][2], ah[0][3], sb + arb0 + ac);
            ldsm_x4(ah[1][0], ah[1][1], ah[1][2], ah[1][3], sb + arb1 + ac);
#pragma unroll
            for (int nt = 0; nt < 4; nt++)
                ldsm_x4(bb[nt][0], bb[nt][1], bb[nt][2], bb[nt][3],
                        sb + MATB + brb[nt] + bc);
#pragma unroll
            for (int mt = 0; mt < 2; mt++)
#pragma unroll
                for (int n8 = 0; n8 < 8; n8++)
                    mma16816(acc[mt][n8], ah[mt],
                             bb[n8 >> 1][(n8 & 1) * 2], bb[n8 >> 1][(n8 & 1) * 2 + 1]);
        }
    }

#pragma unroll
    for (int mt = 0; mt < 2; mt++) {
        const int r0 = m0 + wm * 32 + mt * 16 + (lane >> 2);
#pragma unroll
        for (int n8 = 0; n8 < 8; n8++) {
            const int col = n0 + wn * 64 + n8 * 8 + (lane & 3) * 2;
            const float bz0 = __ldg(bias + col), bz1 = __ldg(bias + col + 1);
            float v0 = lrelu(acc[mt][n8][0] + bz0);
            float v1 = lrelu(acc[mt][n8][1] + bz1);
            float v2 = lrelu(acc[mt][n8][2] + bz0);
            float v3 = lrelu(acc[mt][n8][3] + bz1);
            *(__half2*)(Ch + (size_t)r0 * N + col)       = __floats2half2_rn(v0, v1);
            *(__half2*)(Ch + (size_t)(r0 + 8) * N + col) = __floats2half2_rn(v2, v3);
        }
    }
}

// ---------------------------------------------------------------------------
// fp32 -> fp16, both inputs in one launch: 8 floats -> uint4 of 8 halves.
// ---------------------------------------------------------------------------
__global__ void cvt_both(const float* __restrict__ X, const float* __restrict__ Cn,
                         f16* __restrict__ h, int n8half)
{
    int i = blockIdx.x * blockDim.x + threadIdx.x;
    const int stride = gridDim.x * blockDim.x;
    for (; i < 2 * n8half; i += stride) {
        const float4* src = (i < n8half) ? ((const float4*)X) + 2 * i
                                         : ((const float4*)Cn) + 2 * (i - n8half);
        const float4 v0 = src[0];
        const float4 v1 = src[1];
        __half2 a = __floats2half2_rn(v0.x, v0.y);
        __half2 b = __floats2half2_rn(v0.z, v0.w);
        __half2 c = __floats2half2_rn(v1.x, v1.y);
        __half2 d = __floats2half2_rn(v1.z, v1.w);
        uint4 o;
        o.x = *(uint32_t*)&a; o.y = *(uint32_t*)&b;
        o.z = *(uint32_t*)&c; o.w = *(uint32_t*)&d;
        ((uint4*)h)[i] = o;
    }
}

// ---------------------------------------------------------------------------
// Batched weight transpose: W[K,N] fp32 -> T[N,K] fp16, 4 segments.
// ---------------------------------------------------------------------------
__global__ void transpose_all(const float* __restrict__ W1f, const float* __restrict__ W2f,
                              const float* __restrict__ W3f, const float* __restrict__ Wc1f)
{
    const float* W; f16* T; int K, N;
    switch (blockIdx.z) {
        case 0:  W = W1f;  T = g_w1;  K = DIN;  N = HH1; break;
        case 1:  W = W2f;  T = g_w2;  K = HH1;  N = HH2; break;
        case 2:  W = W3f;  T = g_w3;  K = HH2;  N = HH3; break;
        default: W = Wc1f; T = g_wc1; K = DCBP; N = HC;  break;
    }
    if ((int)blockIdx.x >= N / 32 || (int)blockIdx.y >= K / 32) return;

    __shared__ float t[32][33];
    const int tx = threadIdx.x, ty = threadIdx.y;
    const int n = blockIdx.x * 32 + tx;
#pragma unroll
    for (int r = 0; r < 32; r += 8)
        t[ty + r][tx] = W[(size_t)(blockIdx.y * 32 + ty + r) * N + n];
    __syncthreads();
    const int k2 = blockIdx.y * 32 + tx;
#pragma unroll
    for (int r = 0; r < 32; r += 8) {
        const int n2 = blockIdx.x * 32 + ty + r;
        T[(size_t)n2 * K + k2] = __float2half_rn(t[tx][ty + r]);
    }
}

// ---------------------------------------------------------------------------
// CBP pair-list build (deterministic, no atomics, prep fused in smem).
// ---------------------------------------------------------------------------
__global__ void cbp_build(const int* __restrict__ h1, const int* __restrict__ h2)
{
    __shared__ int   icnt[DCBP];
    __shared__ short ilist[DCBP * 8];
    __shared__ int   h1s[HH3];

    const int tid = threadIdx.x;
    for (int i = tid; i < DCBP; i += 256) icnt[i] = 0;
    for (int i = tid; i < HH3; i += 256) h1s[i] = h1[i];
    __syncthreads();
    if (tid == 0) {
        for (int l = 0; l < HH3; l++) {
            int v = h2[l];
            int c = icnt[v];
            if (c < 8) { ilist[v * 8 + c] = (short)l; icnt[v] = c + 1; }
        }
    }
    __syncthreads();

    const int k = blockIdx.x * 256 + tid;
    int cnt = 0;
    const uint32_t base = (uint32_t)k * 64;
    for (int j = 0; j < HH3; j++) {
        int v = (k - h1s[j]) & (DCBP - 1);
        int c = icnt[v];
        for (int t = 0; t < c; t++) {
            if (cnt < 64)
                g_pairs[base + cnt++] = ((uint32_t)j << 16) | (uint32_t)ilist[v * 8 + t];
        }
    }
    int cnt4 = (cnt + 3) & ~3;
    if (cnt4 > 64) cnt4 = 64;
    for (int t = cnt; t < cnt4; t++) g_pairs[base + t] = (128u << 16) | 128u;
    g_bincnt[k] = cnt4;
}

// ---------------------------------------------------------------------------
// CBP main (warp-cooperative, conflict-free, exact-count quad loop).
// ---------------------------------------------------------------------------
#define CBP_AX_N  (129 * 33)
#define CBP_STG_P 257
#define CBP_SMEM  ((2 * CBP_AX_N + 32 * CBP_STG_P) * 8)

__global__ void __launch_bounds__(256) cbp_main(
    const float* __restrict__ s1, const float* __restrict__ s2)
{
    extern __shared__ uint2 csm[];
    uint2* ax    = csm;
    uint2* cy    = csm + CBP_AX_N;
    uint2* stage = csm + 2 * CBP_AX_N;

    const int b0 = blockIdx.x * 128;
    const int tid = threadIdx.x, w = tid >> 5, lane = tid & 31;

    for (int i = tid; i < 128 * 32; i += 256) {
        const int j = i & 127, sl = i >> 7;
        const size_t ex = (size_t)(b0 + 4 * sl) * HH3 + j;
        const size_t ec = (size_t)(Bsz + b0 + 4 * sl) * HH3 + j;
        uint32_t x0 = (uint32_t)__half_as_ushort(g_e3[ex])
                    | ((uint32_t)__half_as_ushort(g_e3[ex + 128]) << 16);
        uint32_t x1 = (uint32_t)__half_as_ushort(g_e3[ex + 256])
                    | ((uint32_t)__half_as_ushort(g_e3[ex + 384]) << 16);
        uint32_t y0 = (uint32_t)__half_as_ushort(g_e3[ec])
                    | ((uint32_t)__half_as_ushort(g_e3[ec + 128]) << 16);
        uint32_t y1 = (uint32_t)__half_as_ushort(g_e3[ec + 256])
                    | ((uint32_t)__half_as_ushort(g_e3[ec + 384]) << 16);
        if (s1[j] < 0.f) { x0 ^= 0x80008000u; x1 ^= 0x80008000u; }
        if (s2[j] < 0.f) { y0 ^= 0x80008000u; y1 ^= 0x80008000u; }
        ax[j * 33 + sl] = make_uint2(x0, x1);
        cy[j * 33 + sl] = make_uint2(y0, y1);
    }
    if (tid < 32) {
        ax[128 * 33 + tid] = make_uint2(0u, 0u);
        cy[128 * 33 + tid] = make_uint2(0u, 0u);
    }
    __syncthreads();

    const __half2 z2 = __floats2half2_rn(0.f, 0.f);

    for (int c = 0; c < 8; c++) {
        const int colbase = c * 256 + w * 32;
        for (int bi = 0; bi < 32; bi++) {
            const int k = colbase + bi;
            const int nq = __ldg(g_bincnt + k) >> 2;
            const uint4* pp = (const uint4*)(g_pairs + (size_t)k * 64);
            __half2 a01 = z2, a23 = z2, b01 = z2, b23 = z2;
            for (int q = 0; q < nq; q++) {
                const uint4 pv = __ldg(pp + q);
                {
                    const uint2 av = ax[(pv.x >> 16) * 33 + lane];
                    const uint2 cv = cy[(pv.x & 0xffffu) * 33 + lane];
                    a01 = __hfma2(*(const __half2*)&av.x, *(const __half2*)&cv.x, a01);
                    a23 = __hfma2(*(const __half2*)&av.y, *(const __half2*)&cv.y, a23);
                }
                {
                    const uint2 av = ax[(pv.y >> 16) * 33 + lane];
                    const uint2 cv = cy[(pv.y & 0xffffu) * 33 + lane];
                    b01 = __hfma2(*(const __half2*)&av.x, *(const __half2*)&cv.x, b01);
                    b23 = __hfma2(*(const __half2*)&av.y, *(const __half2*)&cv.y, b23);
                }
                {
                    const uint2 av = ax[(pv.z >> 16) * 33 + lane];
                    const uint2 cv = cy[(pv.z & 0xffffu) * 33 + lane];
                    a01 = __hfma2(*(const __half2*)&av.x, *(const __half2*)&cv.x, a01);
                    a23 = __hfma2(*(const __half2*)&av.y, *(const __half2*)&cv.y, a23);
                }
                {
                    const uint2 av = ax[(pv.w >> 16) * 33 + lane];
                    const uint2 cv = cy[(pv.w & 0xffffu) * 33 + lane];
                    b01 = __hfma2(*(const __half2*)&av.x, *(const __half2*)&cv.x, b01);
                    b23 = __hfma2(*(const __half2*)&av.y, *(const __half2*)&cv.y, b23);
                }
            }
            a01 = __hadd2(a01, b01);
            a23 = __hadd2(a23, b23);
            stage[lane * CBP_STG_P + w * 32 + bi] =
                make_uint2(*(const uint32_t*)&a01, *(const uint32_t*)&a23);
        }
        __syncwarp();
        for (int rp = 0; rp < 32; rp++) {
            const uint2 v = stage[rp * CBP_STG_P + w * 32 + lane];
            const __half2 v01 = *(const __half2*)&v.x;
            const __half2 v23 = *(const __half2*)&v.y;
            const size_t rb = (size_t)(b0 + 4 * rp) * DCBP + (c * 256 + w * 32 + lane);
            g_cbp[rb]            = __low2half(v01);
            g_cbp[rb + DCBP]     = __high2half(v01);
            g_cbp[rb + 2 * DCBP] = __low2half(v23);
            g_cbp[rb + 3 * DCBP] = __high2half(v23);
        }
        __syncwarp();
    }
}

// ---------------------------------------------------------------------------
// Head: logits = z @ Wc2 + bc2 (z fp16), softmax. One warp per row, 16 warps.
// ---------------------------------------------------------------------------
__global__ void __launch_bounds__(512) head_kernel(
    const float* __restrict__ Wc2, const float* __restrict__ bc2,
    float* __restrict__ out)
{
    __shared__ float Ws[HC * NCLS];
    __shared__ float bsm[NCLS];

    const int tid = threadIdx.x;
    for (int i = tid; i < HC * NCLS; i += 512) Ws[i] = Wc2[i];
    if (tid < NCLS) bsm[tid] = bc2[tid];
    __syncthreads();

    const int warp = tid >> 5, lane = tid & 31;
    const int row = blockIdx.x * 16 + warp;
    const f16* zr = g_z + (size_t)row * HC;

    float acc[NCLS];
#pragma unroll
    for (int c = 0; c < NCLS; c++) acc[c] = 0.f;
    for (int k = lane * 2; k < HC; k += 64) {
        __half2 zp = *(const __half2*)(zr + k);
        float z0 = __low2float(zp), z1 = __high2float(zp);
#pragma unroll
        for (int c = 0; c < NCLS; c++) {
            acc[c] = fmaf(z0, Ws[k * NCLS + c], acc[c]);
            acc[c] = fmaf(z1, Ws[(k + 1) * NCLS + c], acc[c]);
        }
    }
#pragma unroll
    for (int c = 0; c < NCLS; c++)
        for (int off = 16; off; off >>= 1)
            acc[c] += __shfl_down_sync(0xffffffffu, acc[c], off);

    if (lane == 0) {
        float v[NCLS], m = -1e30f;
#pragma unroll
        for (int c = 0; c < NCLS; c++) { v[c] = acc[c] + bsm[c]; m = fmaxf(m, v[c]); }
        float ssum = 0.f;
#pragma unroll
        for (int c = 0; c < NCLS; c++) { v[c] = expf(v[c] - m); ssum += v[c]; }
        float inv = 1.f / ssum;
        float* o = out + (size_t)row * NCLS;
#pragma unroll
        for (int c = 0; c < NCLS; c++) o[c] = v[c] * inv;
    }
}

// ---------------------------------------------------------------------------
extern "C" void kernel_launch(void* const* d_in, const int* in_sizes, int n_in,
                              void* d_out, int out_size)
{
    const float* X   = (const float*)d_in[0];
    const float* Cn  = (const float*)d_in[1];
    const float* W1  = (const float*)d_in[2];
    const float* b1  = (const float*)d_in[3];
    const float* W2  = (const float*)d_in[4];
    const float* b2  = (const float*)d_in[5];
    const float* W3  = (const float*)d_in[6];
    const float* b3  = (const float*)d_in[7];
    const int*   h1  = (const int*)d_in[8];
    const float* s1  = (const float*)d_in[9];
    const int*   h2  = (const int*)d_in[10];
    const float* s2  = (const float*)d_in[11];
    const float* Wc1 = (const float*)d_in[12];
    const float* bc1 = (const float*)d_in[13];
    const float* Wc2 = (const float*)d_in[14];
    const float* bc2 = (const float*)d_in[15];
    float* out = (float*)d_out;

    f16 *in_, *e1, *e2, *e3, *cbp, *z, *w1, *w2, *w3, *wc1;
    cudaGetSymbolAddress((void**)&in_, g_in);
    cudaGetSymbolAddress((void**)&e1,  g_e1);
    cudaGetSymbolAddress((void**)&e2,  g_e2);
    cudaGetSymbolAddress((void**)&e3,  g_e3);
    cudaGetSymbolAddress((void**)&cbp, g_cbp);
    cudaGetSymbolAddress((void**)&z,   g_z);
    cudaGetSymbolAddress((void**)&w1,  g_w1);
    cudaGetSymbolAddress((void**)&w2,  g_w2);
    cudaGetSymbolAddress((void**)&w3,  g_w3);
    cudaGetSymbolAddress((void**)&wc1, g_wc1);

    constexpr int SMEM = 3 * 32768;
    cudaFuncSetAttribute((const void*)mma_gemm,
                         cudaFuncAttributeMaxDynamicSharedMemorySize, SMEM);
    cudaFuncSetAttribute((const void*)cbp_main,
                         cudaFuncAttributeMaxDynamicSharedMemorySize, CBP_SMEM);

    const int n8h = Bsz * DIN / 8;

    // idx 3 = gemm2 (calibration probe: fixed-overhead measurement).
    cvt_both<<<4096, 256>>>(X, Cn, in_, n8h);                                       // 0
    transpose_all<<<dim3(32, 64, 4), dim3(32, 8)>>>(W1, W2, W3, Wc1);               // 1
    mma_gemm<<<dim3(HH1 / 128, 2 * Bsz / 128), 256, SMEM>>>(                        // 2
        in_, w1, b1, DIN, HH1, e1);
    mma_gemm<<<dim3(HH2 / 128, 2 * Bsz / 128), 256, SMEM>>>(                        // 3 (profiled)
        e1, w2, b2, HH1, HH2, e2);
    mma_gemm<<<dim3(HH3 / 128, 2 * Bsz / 128), 256, SMEM>>>(                        // 4
        e2, w3, b3, HH2, HH3, e3);
    cbp_build<<<8, 256>>>(h1, h2);                                                  // 5
    cbp_main<<<Bsz / 128, 256, CBP_SMEM>>>(s1, s2);                                 // 6
    mma_gemm<<<dim3(HC / 128, Bsz / 128), 256, SMEM>>>(                             // 7
        cbp, wc1, bc1, DCBP, HC, z);
    head_kernel<<<Bsz / 16, 512>>>(Wc2, bc2, out);                                  // 8
}

// round 14
// speedup vs baseline: 1.2871x; 1.1779x over previous
#include <cuda_runtime.h>
#include <cuda_fp16.h>
#include <cstdint>
#include <math.h>

using f16 = __half;

#define Bsz   16384
#define DIN   1024
#define HH1   512
#define HH2   256
#define HH3   128
#define DCBP  2048
#define HC    1024
#define NCLS  10

// ---------------------------------------------------------------------------
// Scratch (allocation-free: __device__ globals). fp16 activations.
// ---------------------------------------------------------------------------
__device__ __align__(128) f16 g_in[(size_t)2 * Bsz * DIN];
__device__ __align__(128) f16 g_e1[(size_t)2 * Bsz * HH1];
__device__ __align__(128) f16 g_e2[(size_t)2 * Bsz * HH2];
__device__ __align__(128) f16 g_e3[(size_t)2 * Bsz * HH3];
__device__ __align__(128) f16 g_cbp[(size_t)Bsz * DCBP];
__device__ __align__(128) f16 g_z[(size_t)Bsz * HC];
// transposed ([N,K]) fp16 weights
__device__ __align__(128) f16 g_w1[HH1 * DIN];
__device__ __align__(128) f16 g_w2[HH2 * HH1];
__device__ __align__(128) f16 g_w3[HH3 * HH2];
__device__ __align__(128) f16 g_wc1[HC * DCBP];
// CBP pair lists: per bin 48 uint16 slots ([0,16) main, [16,48) overflow).
// pair = (j << 8) | l ; sentinel = (128<<8)|128 (operand rows are zero).
__device__ __align__(16) unsigned short g_pairs16[DCBP * 48];
__device__ __align__(16) int g_meta[DCBP];   // cnt4 | (ovcnt << 16)

__device__ __forceinline__ float lrelu(float v) { return v >= 0.f ? v : 0.2f * v; }

__device__ __forceinline__ uint32_t smem_u32(const void* p) {
    uint32_t a;
    asm("{ .reg .u64 t; cvta.to.shared.u64 t, %1; cvt.u32.u64 %0, t; }" : "=r"(a) : "l"(p));
    return a;
}

#define CP16(dst, src) \
    asm volatile("cp.async.cg.shared.global [%0], [%1], 16;" :: "r"(dst), "l"(src) : "memory")
#define CP_COMMIT() asm volatile("cp.async.commit_group;" ::: "memory")
#define CP_WAIT(n)  asm volatile("cp.async.wait_group %0;" :: "n"(n) : "memory")

__device__ __forceinline__ void ldsm_x4(uint32_t& r0, uint32_t& r1, uint32_t& r2,
                                        uint32_t& r3, uint32_t addr) {
    asm volatile("ldmatrix.sync.aligned.m8n8.x4.shared.b16 {%0,%1,%2,%3}, [%4];"
                 : "=r"(r0), "=r"(r1), "=r"(r2), "=r"(r3) : "r"(addr));
}

__device__ __forceinline__ void mma16816(float* d, const uint32_t* a,
                                         uint32_t b0, uint32_t b1) {
    asm volatile(
        "mma.sync.aligned.m16n8k16.row.col.f32.f16.f16.f32 "
        "{%0,%1,%2,%3}, {%4,%5,%6,%7}, {%8,%9}, {%0,%1,%2,%3};"
        : "+f"(d[0]), "+f"(d[1]), "+f"(d[2]), "+f"(d[3])
        : "r"(a[0]), "r"(a[1]), "r"(a[2]), "r"(a[3]), "r"(b0), "r"(b1));
}

// ---------------------------------------------------------------------------
// mma_gemm: C[M,N] = lrelu(A[M,K] @ B^T + bias), fp16 in/out, fp32 acc.
// CTA tile 128x128, BK=64, 3-stage cp.async pipeline, 8 warps (4M x 2N),
// 2 CTA/SM.  XOR-swizzled smem.  (Proven R10/R13 configuration; untouched.)
// ---------------------------------------------------------------------------
__global__ void __launch_bounds__(256, 2) mma_gemm(
    const f16* __restrict__ A, const f16* __restrict__ B,
    const float* __restrict__ bias, int K, int N, f16* __restrict__ Ch)
{
    constexpr int MATB = 128 * 128;
    constexpr int STGB = 2 * MATB;

    extern __shared__ char smem[];
    const uint32_t sbase = smem_u32(smem);

    const int tid  = threadIdx.x;
    const int warp = tid >> 5, lane = tid & 31;
    const int wm = warp & 3;
    const int wn = warp >> 2;
    const int m0 = blockIdx.y * 128, n0 = blockIdx.x * 128;

    const int arow0 = wm * 32 + (lane & 15);
    const uint32_t ahi = (uint32_t)(lane >> 4);
    const uint32_t ar7 = (uint32_t)(arow0 & 7);
    const uint32_t arb0 = (uint32_t)(arow0 * 128);
    const uint32_t arb1 = (uint32_t)((arow0 + 16) * 128);

    const int brow0 = wn * 64 + (lane & 7) + ((lane >> 1) & 8);
    const uint32_t bhi = (uint32_t)((lane >> 3) & 1);
    const uint32_t br7 = (uint32_t)(brow0 & 7);
    uint32_t brb[4];
#pragma unroll
    for (int nt = 0; nt < 4; nt++) brb[nt] = (uint32_t)((brow0 + nt * 16) * 128);

    float acc[2][8][4];
#pragma unroll
    for (int i = 0; i < 2; i++)
#pragma unroll
        for (int j = 0; j < 8; j++)
#pragma unroll
            for (int q = 0; q < 4; q++) acc[i][j][q] = 0.f;

    const int nk = K >> 6;

    auto load_tile = [&](int t, int s) {
        const int kt = t << 6;
        const uint32_t sb = sbase + (uint32_t)s * STGB;
#pragma unroll
        for (int j = 0; j < 8; j++) {
            int i = tid + j * 256;
            int mat = i >> 10;
            int r = (i >> 3) & 127, c = i & 7;
            const f16* src = mat ? (B + (size_t)(n0 + r) * K + kt + c * 8)
                                 : (A + (size_t)(m0 + r) * K + kt + c * 8);
            CP16(sb + (uint32_t)(mat * MATB + r * 128 + ((c ^ (r & 7)) << 4)), src);
        }
        CP_COMMIT();
    };

    load_tile(0, 0);
    if (nk > 1) load_tile(1, 1);

    for (int t = 0; t < nk; t++) {
        if (t + 1 < nk) { CP_WAIT(1); } else { CP_WAIT(0); }
        __syncthreads();

        if (t + 2 < nk) load_tile(t + 2, (t + 2) % 3);

        const uint32_t sb = sbase + (uint32_t)(t % 3) * STGB;

#pragma unroll
        for (int ks = 0; ks < 4; ks++) {
            const uint32_t ac = ((((uint32_t)ks << 1) + ahi) ^ ar7) << 4;
            const uint32_t bc = ((((uint32_t)ks << 1) + bhi) ^ br7) << 4;
            uint32_t ah[2][4], bb[4][4];
            ldsm_x4(ah[0][0], ah[0][1], ah[0][2], ah[0][3], sb + arb0 + ac);
            ldsm_x4(ah[1][0], ah[1][1], ah[1][2], ah[1][3], sb + arb1 + ac);
#pragma unroll
            for (int nt = 0; nt < 4; nt++)
                ldsm_x4(bb[nt][0], bb[nt][1], bb[nt][2], bb[nt][3],
                        sb + MATB + brb[nt] + bc);
#pragma unroll
            for (int mt = 0; mt < 2; mt++)
#pragma unroll
                for (int n8 = 0; n8 < 8; n8++)
                    mma16816(acc[mt][n8], ah[mt],
                             bb[n8 >> 1][(n8 & 1) * 2], bb[n8 >> 1][(n8 & 1) * 2 + 1]);
        }
    }

#pragma unroll
    for (int mt = 0; mt < 2; mt++) {
        const int r0 = m0 + wm * 32 + mt * 16 + (lane >> 2);
#pragma unroll
        for (int n8 = 0; n8 < 8; n8++) {
            const int col = n0 + wn * 64 + n8 * 8 + (lane & 3) * 2;
            const float bz0 = __ldg(bias + col), bz1 = __ldg(bias + col + 1);
            float v0 = lrelu(acc[mt][n8][0] + bz0);
            float v1 = lrelu(acc[mt][n8][1] + bz1);
            float v2 = lrelu(acc[mt][n8][2] + bz0);
            float v3 = lrelu(acc[mt][n8][3] + bz1);
            *(__half2*)(Ch + (size_t)r0 * N + col)       = __floats2half2_rn(v0, v1);
            *(__half2*)(Ch + (size_t)(r0 + 8) * N + col) = __floats2half2_rn(v2, v3);
        }
    }
}

// ---------------------------------------------------------------------------
// fp32 -> fp16, both inputs in one launch.
// ---------------------------------------------------------------------------
__global__ void cvt_both(const float* __restrict__ X, const float* __restrict__ Cn,
                         f16* __restrict__ h, int n8half)
{
    int i = blockIdx.x * blockDim.x + threadIdx.x;
    const int stride = gridDim.x * blockDim.x;
    for (; i < 2 * n8half; i += stride) {
        const float4* src = (i < n8half) ? ((const float4*)X) + 2 * i
                                         : ((const float4*)Cn) + 2 * (i - n8half);
        const float4 v0 = src[0];
        const float4 v1 = src[1];
        __half2 a = __floats2half2_rn(v0.x, v0.y);
        __half2 b = __floats2half2_rn(v0.z, v0.w);
        __half2 c = __floats2half2_rn(v1.x, v1.y);
        __half2 d = __floats2half2_rn(v1.z, v1.w);
        uint4 o;
        o.x = *(uint32_t*)&a; o.y = *(uint32_t*)&b;
        o.z = *(uint32_t*)&c; o.w = *(uint32_t*)&d;
        ((uint4*)h)[i] = o;
    }
}

// ---------------------------------------------------------------------------
// Batched weight transpose: W[K,N] fp32 -> T[N,K] fp16, 4 segments.
// ---------------------------------------------------------------------------
__global__ void transpose_all(const float* __restrict__ W1f, const float* __restrict__ W2f,
                              const float* __restrict__ W3f, const float* __restrict__ Wc1f)
{
    const float* W; f16* T; int K, N;
    switch (blockIdx.z) {
        case 0:  W = W1f;  T = g_w1;  K = DIN;  N = HH1; break;
        case 1:  W = W2f;  T = g_w2;  K = HH1;  N = HH2; break;
        case 2:  W = W3f;  T = g_w3;  K = HH2;  N = HH3; break;
        default: W = Wc1f; T = g_wc1; K = DCBP; N = HC;  break;
    }
    if ((int)blockIdx.x >= N / 32 || (int)blockIdx.y >= K / 32) return;

    __shared__ float t[32][33];
    const int tx = threadIdx.x, ty = threadIdx.y;
    const int n = blockIdx.x * 32 + tx;
#pragma unroll
    for (int r = 0; r < 32; r += 8)
        t[ty + r][tx] = W[(size_t)(blockIdx.y * 32 + ty + r) * N + n];
    __syncthreads();
    const int k2 = blockIdx.y * 32 + tx;
#pragma unroll
    for (int r = 0; r < 32; r += 8) {
        const int n2 = blockIdx.x * 32 + ty + r;
        T[(size_t)n2 * K + k2] = __float2half_rn(t[tx][ty + r]);
    }
}

// ---------------------------------------------------------------------------
// CBP pair-list build: compact uint16 pairs, main[0:16) + overflow[16:48),
// per-bin meta = cnt4 | (ovcnt<<16).  Deterministic, no atomics.
// ---------------------------------------------------------------------------
__global__ void cbp_build(const int* __restrict__ h1, const int* __restrict__ h2)
{
    __shared__ int   icnt[DCBP];
    __shared__ short ilist[DCBP * 8];
    __shared__ int   h1s[HH3];

    const int tid = threadIdx.x;
    for (int i = tid; i < DCBP; i += 256) icnt[i] = 0;
    for (int i = tid; i < HH3; i += 256) h1s[i] = h1[i];
    __syncthreads();
    if (tid == 0) {
        for (int l = 0; l < HH3; l++) {
            int v = h2[l];
            int c = icnt[v];
            if (c < 8) { ilist[v * 8 + c] = (short)l; icnt[v] = c + 1; }
        }
    }
    __syncthreads();

    const int k = blockIdx.x * 256 + tid;
    int cnt = 0;
    unsigned short* dst = g_pairs16 + (size_t)k * 48;
    for (int j = 0; j < HH3; j++) {
        int v = (k - h1s[j]) & (DCBP - 1);
        int c = icnt[v];
        for (int t = 0; t < c; t++) {
            if (cnt < 48)
                dst[cnt++] = (unsigned short)((j << 8) | (int)ilist[v * 8 + t]);
        }
    }
    int main_cnt = cnt < 16 ? cnt : 16;
    int cnt4 = (main_cnt + 3) & ~3;
    for (int t = main_cnt; t < cnt4; t++)
        dst[t] = (unsigned short)((128 << 8) | 128);   // zero-sentinel
    int ov = cnt > 16 ? cnt - 16 : 0;
    g_meta[k] = cnt4 | (ov << 16);
}

// ---------------------------------------------------------------------------
// CBP main (warp-cooperative, conflict-free, SMEM-resident pair lists):
// block = 128 batch rows, 8 warps; warp processes whole bins; lane owns 4 rows
// (uint2 of 2x half2).  Pair quads read via warp-uniform LDS.64 broadcast
// (no per-bin L2 latency chain).  Rare overflow pairs via __ldg.
// ---------------------------------------------------------------------------
#define CBP_AX_N   (129 * 33)               // uint2 entries per operand array
#define CBP_STG_P  257                      // stage row stride (uint2)
#define CBP_PAIR_U 8192                     // pairs smem: 2048 bins x 4 uint2
#define CBP_META_U 1024                     // meta smem: 2048 ints = 1024 uint2
#define CBP_SMEM   ((2 * CBP_AX_N + 32 * CBP_STG_P + CBP_PAIR_U + CBP_META_U) * 8)

__global__ void __launch_bounds__(256) cbp_main(
    const float* __restrict__ s1, const float* __restrict__ s2)
{
    extern __shared__ uint2 csm[];
    uint2* ax    = csm;                              // [j][lane], stride 33
    uint2* cy    = csm + CBP_AX_N;
    uint2* stage = csm + 2 * CBP_AX_N;               // [rowquad][bin], stride 257
    uint2* spr   = csm + 2 * CBP_AX_N + 32 * CBP_STG_P;   // pair quads [bin*4+q]
    uint32_t* smeta = (uint32_t*)(spr + CBP_PAIR_U);

    const int b0 = blockIdx.x * 128;
    const int tid = threadIdx.x, w = tid >> 5, lane = tid & 31;

    // Async-stage pair lists (main 32 B per bin) + meta into smem.
    {
        const uint32_t spr_a = smem_u32(spr);
        for (int c = tid; c < 4096; c += 256) {          // 16 per thread
            int bin = c >> 1, half = c & 1;
            CP16(spr_a + (uint32_t)c * 16,
                 g_pairs16 + (size_t)bin * 48 + half * 8);
        }
        const uint32_t sm_a = smem_u32(smeta);
        for (int c = tid; c < 512; c += 256)             // 2 per thread
            CP16(sm_a + (uint32_t)c * 16, g_meta + c * 4);
        CP_COMMIT();
    }

    // Fill ax/cy: entry (j, sl) packs rows 4sl..4sl+3 of column j, sign applied.
    for (int i = tid; i < 128 * 32; i += 256) {
        const int j = i & 127, sl = i >> 7;
        const size_t ex = (size_t)(b0 + 4 * sl) * HH3 + j;
        const size_t ec = (size_t)(Bsz + b0 + 4 * sl) * HH3 + j;
        uint32_t x0 = (uint32_t)__half_as_ushort(g_e3[ex])
                    | ((uint32_t)__half_as_ushort(g_e3[ex + 128]) << 16);
        uint32_t x1 = (uint32_t)__half_as_ushort(g_e3[ex + 256])
                    | ((uint32_t)__half_as_ushort(g_e3[ex + 384]) << 16);
        uint32_t y0 = (uint32_t)__half_as_ushort(g_e3[ec])
                    | ((uint32_t)__half_as_ushort(g_e3[ec + 128]) << 16);
        uint32_t y1 = (uint32_t)__half_as_ushort(g_e3[ec + 256])
                    | ((uint32_t)__half_as_ushort(g_e3[ec + 384]) << 16);
        if (s1[j] < 0.f) { x0 ^= 0x80008000u; x1 ^= 0x80008000u; }
        if (s2[j] < 0.f) { y0 ^= 0x80008000u; y1 ^= 0x80008000u; }
        ax[j * 33 + sl] = make_uint2(x0, x1);
        cy[j * 33 + sl] = make_uint2(y0, y1);
    }
    if (tid < 32) {                                  // sentinel row j=l=128
        ax[128 * 33 + tid] = make_uint2(0u, 0u);
        cy[128 * 33 + tid] = make_uint2(0u, 0u);
    }
    CP_WAIT(0);
    __syncthreads();

    const __half2 z2 = __floats2half2_rn(0.f, 0.f);

    for (int c = 0; c < 8; c++) {
        const int colbase = c * 256 + w * 32;
        for (int bi = 0; bi < 32; bi++) {
            const int k = colbase + bi;
            const uint32_t meta = smeta[k];
            const int nq = (int)(meta & 0xffffu) >> 2;   // 0..4 quads
            const uint2* pq = spr + k * 4;
            __half2 a01 = z2, a23 = z2, b01 = z2, b23 = z2;
            for (int q = 0; q < nq; q++) {
                const uint2 pv = pq[q];                   // LDS.64 broadcast
                {
                    const uint32_t p = pv.x & 0xffffu;
                    const uint2 av = ax[(p >> 8) * 33 + lane];
                    const uint2 cv = cy[(p & 0xffu) * 33 + lane];
                    a01 = __hfma2(*(const __half2*)&av.x, *(const __half2*)&cv.x, a01);
                    a23 = __hfma2(*(const __half2*)&av.y, *(const __half2*)&cv.y, a23);
                }
                {
                    const uint32_t p = pv.x >> 16;
                    const uint2 av = ax[(p >> 8) * 33 + lane];
                    const uint2 cv = cy[(p & 0xffu) * 33 + lane];
                    b01 = __hfma2(*(const __half2*)&av.x, *(const __half2*)&cv.x, b01);
                    b23 = __hfma2(*(const __half2*)&av.y, *(const __half2*)&cv.y, b23);
                }
                {
                    const uint32_t p = pv.y & 0xffffu;
                    const uint2 av = ax[(p >> 8) * 33 + lane];
                    const uint2 cv = cy[(p & 0xffu) * 33 + lane];
                    a01 = __hfma2(*(const __half2*)&av.x, *(const __half2*)&cv.x, a01);
                    a23 = __hfma2(*(const __half2*)&av.y, *(const __half2*)&cv.y, a23);
                }
                {
                    const uint32_t p = pv.y >> 16;
                    const uint2 av = ax[(p >> 8) * 33 + lane];
                    const uint2 cv = cy[(p & 0xffu) * 33 + lane];
                    b01 = __hfma2(*(const __half2*)&av.x, *(const __half2*)&cv.x, b01);
                    b23 = __hfma2(*(const __half2*)&av.y, *(const __half2*)&cv.y, b23);
                }
            }
            const int ov = (int)(meta >> 16);            // rare (Poisson tail)
            for (int t = 0; t < ov; t++) {
                const uint32_t p = (uint32_t)__ldg(g_pairs16 + (size_t)k * 48 + 16 + t);
                const uint2 av = ax[(p >> 8) * 33 + lane];
                const uint2 cv = cy[(p & 0xffu) * 33 + lane];
                a01 = __hfma2(*(const __half2*)&av.x, *(const __half2*)&cv.x, a01);
                a23 = __hfma2(*(const __half2*)&av.y, *(const __half2*)&cv.y, a23);
            }
            a01 = __hadd2(a01, b01);
            a23 = __hadd2(a23, b23);
            stage[lane * CBP_STG_P + w * 32 + bi] =
                make_uint2(*(const uint32_t*)&a01, *(const uint32_t*)&a23);
        }
        __syncwarp();
        for (int rp = 0; rp < 32; rp++) {
            const uint2 v = stage[rp * CBP_STG_P + w * 32 + lane];
            const __half2 v01 = *(const __half2*)&v.x;
            const __half2 v23 = *(const __half2*)&v.y;
            const size_t rb = (size_t)(b0 + 4 * rp) * DCBP + (c * 256 + w * 32 + lane);
            g_cbp[rb]            = __low2half(v01);
            g_cbp[rb + DCBP]     = __high2half(v01);
            g_cbp[rb + 2 * DCBP] = __low2half(v23);
            g_cbp[rb + 3 * DCBP] = __high2half(v23);
        }
        __syncwarp();
    }
}

// ---------------------------------------------------------------------------
// Head: logits = z @ Wc2 + bc2 (z fp16), softmax. One warp per row, 16 warps.
// ---------------------------------------------------------------------------
__global__ void __launch_bounds__(512) head_kernel(
    const float* __restrict__ Wc2, const float* __restrict__ bc2,
    float* __restrict__ out)
{
    __shared__ float Ws[HC * NCLS];
    __shared__ float bsm[NCLS];

    const int tid = threadIdx.x;
    for (int i = tid; i < HC * NCLS; i += 512) Ws[i] = Wc2[i];
    if (tid < NCLS) bsm[tid] = bc2[tid];
    __syncthreads();

    const int warp = tid >> 5, lane = tid & 31;
    const int row = blockIdx.x * 16 + warp;
    const f16* zr = g_z + (size_t)row * HC;

    float acc[NCLS];
#pragma unroll
    for (int c = 0; c < NCLS; c++) acc[c] = 0.f;
    for (int k = lane * 2; k < HC; k += 64) {
        __half2 zp = *(const __half2*)(zr + k);
        float z0 = __low2float(zp), z1 = __high2float(zp);
#pragma unroll
        for (int c = 0; c < NCLS; c++) {
            acc[c] = fmaf(z0, Ws[k * NCLS + c], acc[c]);
            acc[c] = fmaf(z1, Ws[(k + 1) * NCLS + c], acc[c]);
        }
    }
#pragma unroll
    for (int c = 0; c < NCLS; c++)
        for (int off = 16; off; off >>= 1)
            acc[c] += __shfl_down_sync(0xffffffffu, acc[c], off);

    if (lane == 0) {
        float v[NCLS], m = -1e30f;
#pragma unroll
        for (int c = 0; c < NCLS; c++) { v[c] = acc[c] + bsm[c]; m = fmaxf(m, v[c]); }
        float ssum = 0.f;
#pragma unroll
        for (int c = 0; c < NCLS; c++) { v[c] = expf(v[c] - m); ssum += v[c]; }
        float inv = 1.f / ssum;
        float* o = out + (size_t)row * NCLS;
#pragma unroll
        for (int c = 0; c < NCLS; c++) o[c] = v[c] * inv;
    }
}

// ---------------------------------------------------------------------------
extern "C" void kernel_launch(void* const* d_in, const int* in_sizes, int n_in,
                              void* d_out, int out_size)
{
    const float* X   = (const float*)d_in[0];
    const float* Cn  = (const float*)d_in[1];
    const float* W1  = (const float*)d_in[2];
    const float* b1  = (const float*)d_in[3];
    const float* W2  = (const float*)d_in[4];
    const float* b2  = (const float*)d_in[5];
    const float* W3  = (const float*)d_in[6];
    const float* b3  = (const float*)d_in[7];
    const int*   h1  = (const int*)d_in[8];
    const float* s1  = (const float*)d_in[9];
    const int*   h2  = (const int*)d_in[10];
    const float* s2  = (const float*)d_in[11];
    const float* Wc1 = (const float*)d_in[12];
    const float* bc1 = (const float*)d_in[13];
    const float* Wc2 = (const float*)d_in[14];
    const float* bc2 = (const float*)d_in[15];
    float* out = (float*)d_out;

    f16 *in_, *e1, *e2, *e3, *cbp, *z, *w1, *w2, *w3, *wc1;
    cudaGetSymbolAddress((void**)&in_, g_in);
    cudaGetSymbolAddress((void**)&e1,  g_e1);
    cudaGetSymbolAddress((void**)&e2,  g_e2);
    cudaGetSymbolAddress((void**)&e3,  g_e3);
    cudaGetSymbolAddress((void**)&cbp, g_cbp);
    cudaGetSymbolAddress((void**)&z,   g_z);
    cudaGetSymbolAddress((void**)&w1,  g_w1);
    cudaGetSymbolAddress((void**)&w2,  g_w2);
    cudaGetSymbolAddress((void**)&w3,  g_w3);
    cudaGetSymbolAddress((void**)&wc1, g_wc1);

    constexpr int SMEM = 3 * 32768;
    cudaFuncSetAttribute((const void*)mma_gemm,
                         cudaFuncAttributeMaxDynamicSharedMemorySize, SMEM);
    cudaFuncSetAttribute((const void*)cbp_main,
                         cudaFuncAttributeMaxDynamicSharedMemorySize, CBP_SMEM);

    const int n8h = Bsz * DIN / 8;

    // idx 3 = gemm2 (regression guard).
    cvt_both<<<4096, 256>>>(X, Cn, in_, n8h);                                       // 0
    transpose_all<<<dim3(32, 64, 4), dim3(32, 8)>>>(W1, W2, W3, Wc1);               // 1
    mma_gemm<<<dim3(HH1 / 128, 2 * Bsz / 128), 256, SMEM>>>(                        // 2
        in_, w1, b1, DIN, HH1, e1);
    mma_gemm<<<dim3(HH2 / 128, 2 * Bsz / 128), 256, SMEM>>>(                        // 3 (profiled)
        e1, w2, b2, HH1, HH2, e2);
    mma_gemm<<<dim3(HH3 / 128, 2 * Bsz / 128), 256, SMEM>>>(                        // 4
        e2, w3, b3, HH2, HH3, e3);
    cbp_build<<<8, 256>>>(h1, h2);                                                  // 5
    cbp_main<<<Bsz / 128, 256, CBP_SMEM>>>(s1, s2);                                 // 6
    mma_gemm<<<dim3(HC / 128, Bsz / 128), 256, SMEM>>>(                             // 7
        cbp, wc1, bc1, DCBP, HC, z);
    head_kernel<<<Bsz / 16, 512>>>(Wc2, bc2, out);                                  // 8
}